// round 1
// baseline (speedup 1.0000x reference)
#include <cuda_runtime.h>
#include <cuda_bf16.h>

// Radius-neighbor mean pooling via uniform-grid binning.
//   out[b, o] = mean over {i : |out_pos[o] - inp_pos[i]|^2 <= R^2} of x[b, i]
// Grid cell size == radius (0.05) -> 20^3 cells, 27-cell neighborhood search.

#define RADIUS   0.05f
#define R2       (RADIUS * RADIUS)
#define GRID     20
#define NCELLS   (GRID * GRID * GRID)   // 8000
#define CAP      64                     // max points per cell (lambda~2.05, overflow prob ~1e-63)
#define BCH      8                      // channels (B)

__device__ int g_counts[NCELLS];
__device__ int g_bins[NCELLS * CAP];

__device__ __forceinline__ int cell_coord(float p) {
    int c = (int)(p * (float)GRID);
    if (c < 0) c = 0;
    if (c > GRID - 1) c = GRID - 1;
    return c;
}

// ---------------------------------------------------------------------------
// Kernel 1: bin all input points. Single CTA so counters can live in smem
// (zeroed each launch -> deterministic, no separate memset kernel).
// ---------------------------------------------------------------------------
__global__ void __launch_bounds__(1024, 1)
bin_points_kernel(const float* __restrict__ ipos, int n_in) {
    __shared__ int s_cnt[NCELLS];
    int tid = threadIdx.x;
    for (int c = tid; c < NCELLS; c += blockDim.x) s_cnt[c] = 0;
    __syncthreads();

    for (int i = tid; i < n_in; i += blockDim.x) {
        float px = ipos[i * 3 + 0];
        float py = ipos[i * 3 + 1];
        float pz = ipos[i * 3 + 2];
        int cell = (cell_coord(px) * GRID + cell_coord(py)) * GRID + cell_coord(pz);
        int slot = atomicAdd(&s_cnt[cell], 1);
        if (slot < CAP) g_bins[cell * CAP + slot] = i;
    }
    __syncthreads();

    for (int c = tid; c < NCELLS; c += blockDim.x) {
        int v = s_cnt[c];
        g_counts[c] = v < CAP ? v : CAP;
    }
}

// ---------------------------------------------------------------------------
// Kernel 2: one warp per output point. Lane l (< 27) owns neighbor cell
// (dx,dy,dz) = (l/9-1, (l/3)%3-1, l%3-1), tests its candidates, then the warp
// butterfly-reduces {count, sum[0..7]} and lane 0 writes the 8 outputs.
// ---------------------------------------------------------------------------
__global__ void __launch_bounds__(256)
gather_kernel(const float* __restrict__ x,
              const float* __restrict__ ipos,
              const float* __restrict__ opos,
              float* __restrict__ out,
              int n_in, int n_out) {
    int warp = (blockIdx.x * blockDim.x + threadIdx.x) >> 5;
    int lane = threadIdx.x & 31;
    if (warp >= n_out) return;

    float ox = opos[warp * 3 + 0];
    float oy = opos[warp * 3 + 1];
    float oz = opos[warp * 3 + 2];

    float cnt = 0.0f;
    float s[BCH];
#pragma unroll
    for (int b = 0; b < BCH; b++) s[b] = 0.0f;

    if (lane < 27) {
        int cx = cell_coord(ox) + (lane / 9) - 1;
        int cy = cell_coord(oy) + ((lane / 3) % 3) - 1;
        int cz = cell_coord(oz) + (lane % 3) - 1;
        if (cx >= 0 && cx < GRID && cy >= 0 && cy < GRID && cz >= 0 && cz < GRID) {
            int cell = (cx * GRID + cy) * GRID + cz;
            int c = g_counts[cell];
            int base = cell * CAP;
            for (int t = 0; t < c; t++) {
                int idx = g_bins[base + t];
                float dx = ox - ipos[idx * 3 + 0];
                float dy = oy - ipos[idx * 3 + 1];
                float dz = oz - ipos[idx * 3 + 2];
                float d2 = fmaf(dx, dx, fmaf(dy, dy, dz * dz));
                if (d2 <= R2) {
                    cnt += 1.0f;
#pragma unroll
                    for (int b = 0; b < BCH; b++)
                        s[b] += x[b * n_in + idx];
                }
            }
        }
    }

    // warp reduction of 9 values
#pragma unroll
    for (int off = 16; off > 0; off >>= 1) {
        cnt += __shfl_xor_sync(0xFFFFFFFFu, cnt, off);
#pragma unroll
        for (int b = 0; b < BCH; b++)
            s[b] += __shfl_xor_sync(0xFFFFFFFFu, s[b], off);
    }

    if (lane == 0) {
        float dem = cnt > 0.0f ? cnt : 1.0f;
        float inv = 1.0f / dem;
#pragma unroll
        for (int b = 0; b < BCH; b++)
            out[b * n_out + warp] = s[b] * inv;
    }
}

// ---------------------------------------------------------------------------
extern "C" void kernel_launch(void* const* d_in, const int* in_sizes, int n_in_arr,
                              void* d_out, int out_size) {
    const float* x    = (const float*)d_in[0];   // [B, n_in]
    const float* ipos = (const float*)d_in[1];   // [n_in, 3]
    const float* opos = (const float*)d_in[2];   // [n_out, 3]
    float* out = (float*)d_out;                  // [B, n_out]

    int n_in  = in_sizes[1] / 3;
    int n_out = in_sizes[2] / 3;

    bin_points_kernel<<<1, 1024>>>(ipos, n_in);

    int total_threads = n_out * 32;
    int block = 256;
    int grid = (total_threads + block - 1) / block;
    gather_kernel<<<grid, block>>>(x, ipos, opos, out, n_in, n_out);
}

// round 2
// speedup vs baseline: 2.1253x; 2.1253x over previous
#include <cuda_runtime.h>
#include <cuda_bf16.h>

// Radius-neighbor mean pooling via uniform-grid binning, fully parallel.
//   out[b, o] = mean over {i : |out_pos[o] - inp_pos[i]|^2 <= R^2} of x[b, i]
//
// Bin entries carry position + all 8 channel values (48B records), so the
// gather inner loop is 3 contiguous LDG.128 per candidate with no indirection.

#define RADIUS   0.05f
#define R2       (RADIUS * RADIUS)
#define GRID     20
#define NCELLS   (GRID * GRID * GRID)   // 8000
#define CAP      64                     // lambda ~2.05 pts/cell; P(>=64) ~ 1e-63
#define BCH      8                      // channels (B)
#define EFLOATS  12                     // 3 pos + 8 ch + 1 pad = 48 bytes

__device__ int   g_counts[NCELLS];
__device__ float g_bins[NCELLS * CAP * EFLOATS];   // ~24.6 MB, sparsely touched

__device__ __forceinline__ int cell_coord(float p) {
    int c = (int)(p * (float)GRID);
    if (c < 0) c = 0;
    if (c > GRID - 1) c = GRID - 1;
    return c;
}

// ---------------------------------------------------------------------------
// Kernel 0: zero the per-cell counters (device globals are only zeroed at
// module load; every replay must start clean).
// ---------------------------------------------------------------------------
__global__ void zero_counts_kernel() {
    int i = blockIdx.x * blockDim.x + threadIdx.x;
    if (i < NCELLS) g_counts[i] = 0;
}

// ---------------------------------------------------------------------------
// Kernel 1: bin all input points (multi-CTA, global atomics). Each thread
// owns one input point: reads its position (AoS) and its 8 channel values
// (coalesced across threads within each channel row), writes one 48B record.
// ---------------------------------------------------------------------------
__global__ void __launch_bounds__(256)
bin_points_kernel(const float* __restrict__ x,
                  const float* __restrict__ ipos,
                  int n_in) {
    int i = blockIdx.x * blockDim.x + threadIdx.x;
    if (i >= n_in) return;

    float px = ipos[i * 3 + 0];
    float py = ipos[i * 3 + 1];
    float pz = ipos[i * 3 + 2];
    int cell = (cell_coord(px) * GRID + cell_coord(py)) * GRID + cell_coord(pz);

    int slot = atomicAdd(&g_counts[cell], 1);
    if (slot >= CAP) return;   // statistically unreachable

    float c0 = x[0 * n_in + i];
    float c1 = x[1 * n_in + i];
    float c2 = x[2 * n_in + i];
    float c3 = x[3 * n_in + i];
    float c4 = x[4 * n_in + i];
    float c5 = x[5 * n_in + i];
    float c6 = x[6 * n_in + i];
    float c7 = x[7 * n_in + i];

    float4* e = (float4*)&g_bins[(cell * CAP + slot) * EFLOATS];
    e[0] = make_float4(px, py, pz, c0);
    e[1] = make_float4(c1, c2, c3, c4);
    e[2] = make_float4(c5, c6, c7, 0.0f);
}

// ---------------------------------------------------------------------------
// Kernel 2: one warp per output point. Lane l (< 27) owns one of the 27
// neighbor cells, tests its candidates (3x LDG.128 each, no indirection),
// then the warp butterfly-reduces {count, sum[0..7]}; lane 0 writes 8 outputs.
// ---------------------------------------------------------------------------
__global__ void __launch_bounds__(256)
gather_kernel(const float* __restrict__ opos,
              float* __restrict__ out,
              int n_out) {
    int warp = (blockIdx.x * blockDim.x + threadIdx.x) >> 5;
    int lane = threadIdx.x & 31;
    if (warp >= n_out) return;

    float ox = opos[warp * 3 + 0];
    float oy = opos[warp * 3 + 1];
    float oz = opos[warp * 3 + 2];

    float cnt = 0.0f;
    float s[BCH];
#pragma unroll
    for (int b = 0; b < BCH; b++) s[b] = 0.0f;

    if (lane < 27) {
        int cx = cell_coord(ox) + (lane / 9) - 1;
        int cy = cell_coord(oy) + ((lane / 3) % 3) - 1;
        int cz = cell_coord(oz) + (lane % 3) - 1;
        if (cx >= 0 && cx < GRID && cy >= 0 && cy < GRID && cz >= 0 && cz < GRID) {
            int cell = (cx * GRID + cy) * GRID + cz;
            int c = g_counts[cell];
            if (c > CAP) c = CAP;
            const float4* base = (const float4*)&g_bins[cell * CAP * EFLOATS];
            for (int t = 0; t < c; t++) {
                float4 e0 = base[t * 3 + 0];
                float4 e1 = base[t * 3 + 1];
                float4 e2 = base[t * 3 + 2];
                float dx = ox - e0.x;
                float dy = oy - e0.y;
                float dz = oz - e0.z;
                float d2 = fmaf(dx, dx, fmaf(dy, dy, dz * dz));
                if (d2 <= R2) {
                    cnt  += 1.0f;
                    s[0] += e0.w;
                    s[1] += e1.x;  s[2] += e1.y;  s[3] += e1.z;  s[4] += e1.w;
                    s[5] += e2.x;  s[6] += e2.y;  s[7] += e2.z;
                }
            }
        }
    }

    // warp reduction of 9 values
#pragma unroll
    for (int off = 16; off > 0; off >>= 1) {
        cnt += __shfl_xor_sync(0xFFFFFFFFu, cnt, off);
#pragma unroll
        for (int b = 0; b < BCH; b++)
            s[b] += __shfl_xor_sync(0xFFFFFFFFu, s[b], off);
    }

    if (lane == 0) {
        float dem = cnt > 0.0f ? cnt : 1.0f;
        float inv = 1.0f / dem;
#pragma unroll
        for (int b = 0; b < BCH; b++)
            out[b * n_out + warp] = s[b] * inv;
    }
}

// ---------------------------------------------------------------------------
extern "C" void kernel_launch(void* const* d_in, const int* in_sizes, int n_in_arr,
                              void* d_out, int out_size) {
    const float* x    = (const float*)d_in[0];   // [B, n_in]
    const float* ipos = (const float*)d_in[1];   // [n_in, 3]
    const float* opos = (const float*)d_in[2];   // [n_out, 3]
    float* out = (float*)d_out;                  // [B, n_out]

    int n_in  = in_sizes[1] / 3;
    int n_out = in_sizes[2] / 3;

    zero_counts_kernel<<<(NCELLS + 255) / 256, 256>>>();

    bin_points_kernel<<<(n_in + 255) / 256, 256>>>(x, ipos, n_in);

    int total_threads = n_out * 32;
    int block = 256;
    int grid = (total_threads + block - 1) / block;
    gather_kernel<<<grid, block>>>(opos, out, n_out);
}